// round 3
// baseline (speedup 1.0000x reference)
#include <cuda_runtime.h>
#include <math.h>

// ---------------- problem constants ----------------
#define BATCH  4
#define TSEQ   512
#define KDIM   512
#define HEADS  8
#define NBLK   4
#define VOCAB  32000
#define FFDIM  2048
#define BT     (BATCH*TSEQ)     // 2048 rows

// ---------------- scratch (device global, no runtime alloc) ----------------
#define SZ_H    (2048L*512)        // hidden
#define SZ_QKV  (2048L*4096)       // q / k / v / y
#define SZ_ATT  (32L*512*512)      // [b*h][q][s]
#define SZ_T1   (2048L*512)
#define SZ_FF   (2048L*2048)

#define OFF_H   0L
#define OFF_Q   (OFF_H   + SZ_H)
#define OFF_K   (OFF_Q   + SZ_QKV)
#define OFF_V   (OFF_K   + SZ_QKV)
#define OFF_ATT (OFF_V   + SZ_QKV)
#define OFF_Y   (OFF_ATT + SZ_ATT)
#define OFF_T1  (OFF_Y   + SZ_QKV)
#define OFF_FF  (OFF_T1  + SZ_T1)
#define SCRATCH_TOTAL (OFF_FF + SZ_FF)   // 48,234,496 floats (~184 MiB)

__device__ float g_scratch[SCRATCH_TOTAL];

// ---------------- helpers ----------------
__device__ __forceinline__ float warpRedSum(float v) {
    #pragma unroll
    for (int o = 16; o > 0; o >>= 1) v += __shfl_xor_sync(0xffffffffu, v, o);
    return v;
}
__device__ __forceinline__ float warpRedMax(float v) {
    #pragma unroll
    for (int o = 16; o > 0; o >>= 1) v = fmaxf(v, __shfl_xor_sync(0xffffffffu, v, o));
    return v;
}
__device__ __forceinline__ float gelu_exact(float x) {
    return 0.5f * x * (1.0f + erff(x * 0.70710678118654752f));
}

// ---------------- generic tiled SGEMM ----------------
// C[M,N] = alpha * A[M,K] * B   (+ bias[n]) (+ GELU)
// TB==0 : B is row-major [K,N], element (k,n) at B[k*ldb + n]
// TB==1 : B accessed transposed, element (k,n) at B[n*ldb + k]
// CAUSAL==1 : (scores) skip whole tiles strictly above the diagonal
// CAUSAL==2 : (att@V)  limit k-loop to k < m0+BM  (att rows are zero beyond q)
// Batch z = blockIdx.z is decomposed as bb = z/Hdiv, hh = z%Hdiv with
// per-operand strides (sXb, sXh) -> supports [b,t,h,d] layouts without copies.
#define BM 128
#define BN 128
#define BK 8

template<int TB, int ACT, int CAUSAL>
__global__ __launch_bounds__(256)
void sgemm_kernel(const float* __restrict__ A, int lda, long sAb, long sAh,
                  const float* __restrict__ Bm, int ldb, long sBb, long sBh,
                  const float* __restrict__ bias,
                  float* __restrict__ C, int ldc, long sCb, long sCh,
                  int M, int N, int Kd, int Hdiv, float alpha)
{
    const int bx = blockIdx.x, by = blockIdx.y, bz = blockIdx.z;
    if (CAUSAL == 1 && bx > by) return;   // fully-masked score tile

    const int bb = bz / Hdiv, hh = bz % Hdiv;
    A  += (long)bb * sAb + (long)hh * sAh;
    Bm += (long)bb * sBb + (long)hh * sBh;
    C  += (long)bb * sCb + (long)hh * sCh;

    __shared__ float As[2][BK][BM];
    __shared__ float Bs[2][BK][BN];

    const int tid = threadIdx.x;
    const int m0 = by * BM, n0 = bx * BN;

    int nk = Kd / BK;
    if (CAUSAL == 2) {
        int klim = m0 + BM; if (klim > Kd) klim = Kd;
        nk = (klim + BK - 1) / BK;
    }

    // A tile load mapping: 128 rows x 8 k  -> thread loads one float4
    const int arow = tid >> 1;            // 0..127
    const int acol = (tid & 1) * 4;       // 0 or 4
    const float* Aload = A + (long)(m0 + arow) * lda + acol;

    // B tile load mapping
    int brow, bcol;
    const float* Bload;
    if (TB) { brow = tid >> 1;  bcol = (tid & 1)  * 4; Bload = Bm + (long)(n0 + brow) * ldb + bcol; }
    else    { brow = tid >> 5;  bcol = (tid & 31) * 4; Bload = Bm + (long)brow * ldb + n0 + bcol; }

    // prologue: tile 0
    {
        float4 av = *(const float4*)(Aload);
        As[0][acol+0][arow] = av.x; As[0][acol+1][arow] = av.y;
        As[0][acol+2][arow] = av.z; As[0][acol+3][arow] = av.w;
        float4 bv = *(const float4*)(Bload);
        if (TB) {
            Bs[0][bcol+0][brow] = bv.x; Bs[0][bcol+1][brow] = bv.y;
            Bs[0][bcol+2][brow] = bv.z; Bs[0][bcol+3][brow] = bv.w;
        } else {
            *(float4*)&Bs[0][brow][bcol] = bv;
        }
    }
    __syncthreads();

    float acc[8][8];
    #pragma unroll
    for (int i = 0; i < 8; i++)
        #pragma unroll
        for (int j = 0; j < 8; j++) acc[i][j] = 0.0f;

    const int mb = (tid >> 4) * 8;   // 0..120
    const int nb = (tid & 15) * 8;   // 0..120

    for (int kt = 0; kt < nk; kt++) {
        const int buf = kt & 1;
        const bool pf = (kt + 1 < nk);
        float4 av, bv;
        if (pf) {
            av = *(const float4*)(Aload + (kt + 1) * BK);
            bv = TB ? *(const float4*)(Bload + (kt + 1) * BK)
                    : *(const float4*)(Bload + (long)(kt + 1) * BK * ldb);
        }
        #pragma unroll
        for (int kk = 0; kk < BK; kk++) {
            float a[8], b[8];
            *(float4*)(a)     = *(float4*)&As[buf][kk][mb];
            *(float4*)(a + 4) = *(float4*)&As[buf][kk][mb + 4];
            *(float4*)(b)     = *(float4*)&Bs[buf][kk][nb];
            *(float4*)(b + 4) = *(float4*)&Bs[buf][kk][nb + 4];
            #pragma unroll
            for (int i = 0; i < 8; i++)
                #pragma unroll
                for (int j = 0; j < 8; j++)
                    acc[i][j] += a[i] * b[j];
        }
        if (pf) {
            const int nbuf = buf ^ 1;
            As[nbuf][acol+0][arow] = av.x; As[nbuf][acol+1][arow] = av.y;
            As[nbuf][acol+2][arow] = av.z; As[nbuf][acol+3][arow] = av.w;
            if (TB) {
                Bs[nbuf][bcol+0][brow] = bv.x; Bs[nbuf][bcol+1][brow] = bv.y;
                Bs[nbuf][bcol+2][brow] = bv.z; Bs[nbuf][bcol+3][brow] = bv.w;
            } else {
                *(float4*)&Bs[nbuf][brow][bcol] = bv;
            }
        }
        __syncthreads();
    }

    // epilogue
    float bvv[8];
    if (bias) {
        #pragma unroll
        for (int j = 0; j < 8; j++) bvv[j] = bias[n0 + nb + j];
    } else {
        #pragma unroll
        for (int j = 0; j < 8; j++) bvv[j] = 0.0f;
    }
    #pragma unroll
    for (int i = 0; i < 8; i++) {
        float o[8];
        #pragma unroll
        for (int j = 0; j < 8; j++) {
            float v = acc[i][j] * alpha + bvv[j];
            if (ACT == 1) v = gelu_exact(v);
            o[j] = v;
        }
        float* cp = C + (long)(m0 + mb + i) * ldc + n0 + nb;
        *(float4*)(cp)     = *(float4*)(o);
        *(float4*)(cp + 4) = *(float4*)(o + 4);
    }
}

// ---------------- embedding + sinusoidal positional encoding ----------------
__global__ void embed_kernel(const int* __restrict__ x,
                             const float* __restrict__ eW,
                             float* __restrict__ h)
{
    long i = (long)blockIdx.x * blockDim.x + threadIdx.x;  // BT*K threads
    int d  = (int)(i & (KDIM - 1));
    long bt = i >> 9;                 // K = 512
    int t  = (int)(bt & (TSEQ - 1));
    int tok = x[bt];
    int j = d >> 1;
    // div = 10000 ** (2*(2j)/K) = 10000 ** (j/128)
    float div = powf(10000.0f, (float)j * (1.0f / 128.0f));
    float ang = (float)t / div;
    float p = (d & 1) ? cosf(ang) : sinf(ang);
    h[i] = eW[(long)tok * KDIM + d] + p;
}

// ---------------- causal softmax (row = one (b,h,q)) ----------------
__global__ __launch_bounds__(256)
void softmax_causal_kernel(float* __restrict__ att)
{
    __shared__ float red[8];
    const int r = blockIdx.x;                 // 0 .. B*H*T-1
    const int q = r & (TSEQ - 1);
    float* row = att + (long)r * TSEQ;
    const int tid = threadIdx.x;              // 256 threads, 2 elems each

    float x0 = (tid       <= q) ? row[tid]       : -3.0e38f;
    float x1 = (tid + 256 <= q) ? row[tid + 256] : -3.0e38f;

    float m = warpRedMax(fmaxf(x0, x1));
    if ((tid & 31) == 0) red[tid >> 5] = m;
    __syncthreads();
    m = red[0];
    #pragma unroll
    for (int i = 1; i < 8; i++) m = fmaxf(m, red[i]);
    __syncthreads();

    float e0 = (tid       <= q) ? expf(x0 - m) : 0.0f;
    float e1 = (tid + 256 <= q) ? expf(x1 - m) : 0.0f;

    float s = warpRedSum(e0 + e1);
    if ((tid & 31) == 0) red[tid >> 5] = s;
    __syncthreads();
    s = red[0];
    #pragma unroll
    for (int i = 1; i < 8; i++) s += red[i];

    float inv = 1.0f / s;
    row[tid]       = e0 * inv;   // zeros the masked region too (att@V reads it)
    row[tid + 256] = e1 * inv;
}

// ---------------- (residual +) LayerNorm, K=512, one block per row ----------
__global__ __launch_bounds__(256)
void ln_kernel(const float* __restrict__ in, const float* __restrict__ res,
               const float* __restrict__ w,  const float* __restrict__ b,
               float* __restrict__ out)
{
    __shared__ float red[8];
    const int r = blockIdx.x, tid = threadIdx.x;
    const long base = (long)r * KDIM;

    float x0 = in[base + tid], x1 = in[base + tid + 256];
    if (res) { x0 += res[base + tid]; x1 += res[base + tid + 256]; }

    float s = warpRedSum(x0 + x1);
    if ((tid & 31) == 0) red[tid >> 5] = s;
    __syncthreads();
    float tot = red[0];
    #pragma unroll
    for (int i = 1; i < 8; i++) tot += red[i];
    float mean = tot * (1.0f / (float)KDIM);
    __syncthreads();

    float d0 = x0 - mean, d1 = x1 - mean;
    float s2 = warpRedSum(d0 * d0 + d1 * d1);
    if ((tid & 31) == 0) red[tid >> 5] = s2;
    __syncthreads();
    float v = red[0];
    #pragma unroll
    for (int i = 1; i < 8; i++) v += red[i];
    v *= (1.0f / (float)KDIM);

    float inv = 1.0f / sqrtf(v + 1e-5f);
    out[base + tid]       = d0 * inv * w[tid]       + b[tid];
    out[base + tid + 256] = d1 * inv * w[tid + 256] + b[tid + 256];
}

// ---------------- launch ----------------
extern "C" void kernel_launch(void* const* d_in, const int* in_sizes, int n_in,
                              void* d_out, int out_size)
{
    (void)in_sizes; (void)n_in; (void)out_size;

    const int*   x      = (const int*)  d_in[0];
    const float* embedW = (const float*)d_in[1];
    const float* Wq     = (const float*)d_in[2];
    const float* Wk     = (const float*)d_in[3];
    const float* Wv     = (const float*)d_in[4];
    const float* Wu     = (const float*)d_in[5];
    const float* bu     = (const float*)d_in[6];
    const float* W1     = (const float*)d_in[7];
    const float* b1     = (const float*)d_in[8];
    const float* W2     = (const float*)d_in[9];
    const float* b2     = (const float*)d_in[10];
    const float* ln1w   = (const float*)d_in[11];
    const float* ln1b   = (const float*)d_in[12];
    const float* ln2w   = (const float*)d_in[13];
    const float* ln2b   = (const float*)d_in[14];
    const float* lnfw   = (const float*)d_in[15];
    const float* lnfb   = (const float*)d_in[16];
    const float* uW     = (const float*)d_in[17];
    const float* ub     = (const float*)d_in[18];
    float* outp = (float*)d_out;

    void* sp = nullptr;
    cudaGetSymbolAddress(&sp, g_scratch);
    float* S    = (float*)sp;
    float* hbuf = S + OFF_H;
    float* qb   = S + OFF_Q;
    float* kb   = S + OFF_K;
    float* vb   = S + OFF_V;
    float* attb = S + OFF_ATT;
    float* yb   = S + OFF_Y;
    float* t1   = S + OFF_T1;
    float* ffb  = S + OFF_FF;

    const float inv_sqrt_k = 0.04419417382415922f;  // 1/sqrt(512)

    embed_kernel<<<(BT * KDIM) / 256, 256>>>(x, embedW, hbuf);

    const dim3 blk(256);
    const dim3 gQKV(4096 / BN, BT / BM, 1);          // 32 x 16
    const dim3 gATT(TSEQ / BN, TSEQ / BM, BATCH * HEADS);  // 4 x 4 x 32
    const dim3 gOUT(512  / BN, BT / BM, 1);          // 4 x 16
    const dim3 gFF1(FFDIM / BN, BT / BM, 1);         // 16 x 16

    for (int i = 0; i < NBLK; i++) {
        const long wqkvOff = (long)i * KDIM * (KDIM * HEADS);  // 2,097,152
        const long w1Off   = (long)i * KDIM * FFDIM;           // 1,048,576
        const long w2Off   = (long)i * FFDIM * KDIM;

        // QKV projections: [2048,512] x [512,4096]
        sgemm_kernel<0,0,0><<<gQKV, blk>>>(hbuf, KDIM, 0, 0,
            Wq + wqkvOff, KDIM*HEADS, 0, 0, nullptr,
            qb, KDIM*HEADS, 0, 0, BT, KDIM*HEADS, KDIM, 1, 1.0f);
        sgemm_kernel<0,0,0><<<gQKV, blk>>>(hbuf, KDIM, 0, 0,
            Wk + wqkvOff, KDIM*HEADS, 0, 0, nullptr,
            kb, KDIM*HEADS, 0, 0, BT, KDIM*HEADS, KDIM, 1, 1.0f);
        sgemm_kernel<0,0,0><<<gQKV, blk>>>(hbuf, KDIM, 0, 0,
            Wv + wqkvOff, KDIM*HEADS, 0, 0, nullptr,
            vb, KDIM*HEADS, 0, 0, BT, KDIM*HEADS, KDIM, 1, 1.0f);

        // scores[z][q][s] = (Q . K) / sqrt(k), z = b*H + h, causal tile skip
        sgemm_kernel<1,0,1><<<gATT, blk>>>(
            qb, KDIM*HEADS, (long)TSEQ*KDIM*HEADS, (long)KDIM,
            kb, KDIM*HEADS, (long)TSEQ*KDIM*HEADS, (long)KDIM,
            nullptr,
            attb, TSEQ, (long)HEADS*TSEQ*TSEQ, (long)TSEQ*TSEQ,
            TSEQ, TSEQ, KDIM, HEADS, inv_sqrt_k);

        softmax_causal_kernel<<<BATCH * HEADS * TSEQ, blk>>>(attb);

        // y[b,q,h,d] = att @ V, k-loop limited by causal zero structure
        sgemm_kernel<0,0,2><<<gATT, blk>>>(
            attb, TSEQ, (long)HEADS*TSEQ*TSEQ, (long)TSEQ*TSEQ,
            vb, KDIM*HEADS, (long)TSEQ*KDIM*HEADS, (long)KDIM,
            nullptr,
            yb, KDIM*HEADS, (long)TSEQ*KDIM*HEADS, (long)KDIM,
            TSEQ, TSEQ, KDIM, HEADS, 1.0f);

        // attn out proj: [2048,4096] x [4096,512] + bu
        sgemm_kernel<0,0,0><<<gOUT, blk>>>(yb, KDIM*HEADS, 0, 0,
            Wu + wqkvOff, KDIM, 0, 0, bu + (long)i*KDIM,
            t1, KDIM, 0, 0, BT, KDIM, KDIM*HEADS, 1, 1.0f);

        // h = LN(attn_out + h)
        ln_kernel<<<BT, blk>>>(t1, hbuf, ln1w + (long)i*KDIM, ln1b + (long)i*KDIM, hbuf);

        // FFN up + exact GELU: [2048,512] x [512,2048]
        sgemm_kernel<0,1,0><<<gFF1, blk>>>(hbuf, KDIM, 0, 0,
            W1 + w1Off, FFDIM, 0, 0, b1 + (long)i*FFDIM,
            ffb, FFDIM, 0, 0, BT, FFDIM, KDIM, 1, 1.0f);

        // FFN down: [2048,2048] x [2048,512]
        sgemm_kernel<0,0,0><<<gOUT, blk>>>(ffb, FFDIM, 0, 0,
            W2 + w2Off, KDIM, 0, 0, b2 + (long)i*KDIM,
            t1, KDIM, 0, 0, BT, KDIM, FFDIM, 1, 1.0f);

        // h = LN(ff_out + h)
        ln_kernel<<<BT, blk>>>(t1, hbuf, ln2w + (long)i*KDIM, ln2b + (long)i*KDIM, hbuf);
    }

    // final LN (no residual)
    ln_kernel<<<BT, blk>>>(hbuf, nullptr, lnfw, lnfb, hbuf);

    // unembed: [2048,512] x [512,32000] + b
    const dim3 gUN(VOCAB / BN, BT / BM, 1);  // 250 x 16
    sgemm_kernel<0,0,0><<<gUN, blk>>>(hbuf, KDIM, 0, 0,
        uW, VOCAB, 0, 0, ub,
        outp, VOCAB, 0, 0, BT, VOCAB, KDIM, 1, 1.0f);
}